// round 1
// baseline (speedup 1.0000x reference)
#include <cuda_runtime.h>
#include <math.h>

#define BATCH 2
#define SEQ 2048
#define NH 16
#define HD 64
#define DM 1024
#define WINDOW 512
#define MTOT (BATCH*SEQ)      // 4096
#define NQKV (3*DM)           // 3072

#define BQ 64
#define BKV 64
#define SPITCH 65

// scratch (allocation-free contract: __device__ globals)
__device__ float g_qkv[(size_t)MTOT * NQKV];   // (b*s, 3*H*hd)
__device__ float g_attn[(size_t)MTOT * DM];    // (b*s, H*hd) attention output

// ---------------------------------------------------------------------------
// SGEMM: C[M,N] = A[M,K] @ B[K,N] + bias[N]   (all row-major, dims % 128 == 0)
// 128x128 block tile, BK=8, 256 threads, 8x8 per thread
// ---------------------------------------------------------------------------
__global__ __launch_bounds__(256) void sgemm_bias_kernel(
    const float* __restrict__ A, const float* __restrict__ B,
    const float* __restrict__ bias, float* __restrict__ C,
    int M, int N, int K)
{
    __shared__ float As[8][128];
    __shared__ float Bs[8][128];

    const int tid = threadIdx.x;
    const int tx = tid & 15;          // 0..15  (N direction)
    const int ty = tid >> 4;          // 0..15  (M direction)
    const int rowBase = blockIdx.y * 128;
    const int colBase = blockIdx.x * 128;

    float acc[8][8];
#pragma unroll
    for (int i = 0; i < 8; i++)
#pragma unroll
        for (int j = 0; j < 8; j++) acc[i][j] = 0.f;

    const int aRow = tid >> 1;            // 0..127
    const int aCol = (tid & 1) * 4;       // 0 or 4
    const int bRow = tid >> 5;            // 0..7
    const int bCol = (tid & 31) * 4;      // 0..124

    const float* Aptr = A + (size_t)(rowBase + aRow) * K + aCol;
    const float* Bptr = B + (size_t)bRow * N + colBase + bCol;

    for (int k0 = 0; k0 < K; k0 += 8) {
        float4 av = *reinterpret_cast<const float4*>(Aptr + k0);
        As[aCol + 0][aRow] = av.x;
        As[aCol + 1][aRow] = av.y;
        As[aCol + 2][aRow] = av.z;
        As[aCol + 3][aRow] = av.w;
        float4 bv = *reinterpret_cast<const float4*>(Bptr + (size_t)k0 * N);
        *reinterpret_cast<float4*>(&Bs[bRow][bCol]) = bv;
        __syncthreads();

#pragma unroll
        for (int kk = 0; kk < 8; kk++) {
            float4 a0 = *reinterpret_cast<const float4*>(&As[kk][ty * 8]);
            float4 a1 = *reinterpret_cast<const float4*>(&As[kk][ty * 8 + 4]);
            float4 b0 = *reinterpret_cast<const float4*>(&Bs[kk][tx * 8]);
            float4 b1 = *reinterpret_cast<const float4*>(&Bs[kk][tx * 8 + 4]);
            float a[8] = {a0.x, a0.y, a0.z, a0.w, a1.x, a1.y, a1.z, a1.w};
            float b[8] = {b0.x, b0.y, b0.z, b0.w, b1.x, b1.y, b1.z, b1.w};
#pragma unroll
            for (int i = 0; i < 8; i++)
#pragma unroll
                for (int j = 0; j < 8; j++)
                    acc[i][j] = fmaf(a[i], b[j], acc[i][j]);
        }
        __syncthreads();
    }

#pragma unroll
    for (int i = 0; i < 8; i++) {
        size_t r = (size_t)(rowBase + ty * 8 + i);
#pragma unroll
        for (int j = 0; j < 8; j += 4) {
            int c = colBase + tx * 8 + j;
            float4 o;
            o.x = acc[i][j + 0] + bias[c + 0];
            o.y = acc[i][j + 1] + bias[c + 1];
            o.z = acc[i][j + 2] + bias[c + 2];
            o.w = acc[i][j + 3] + bias[c + 3];
            *reinterpret_cast<float4*>(C + r * N + c) = o;
        }
    }
}

// ---------------------------------------------------------------------------
// Sliding-window attention (flash-style, fp32).
// Block = (b, h, 64-query tile). 128 threads: ty=tid/8 (16 row groups x 4 rows),
// tx=tid%8; columns per thread are cj = tx + 8*j (conflict-free smem reads).
// qkv layout per row m=b*SEQ+s: [Q(0..1023) | K(1024..2047) | V(2048..3071)],
// head h at offset h*64 within each 1024 chunk.
// ---------------------------------------------------------------------------
__global__ __launch_bounds__(128) void swa_kernel(const float* __restrict__ qkv,
                                                  float* __restrict__ outp)
{
    extern __shared__ float sm[];
    float* Qs = sm;                        // [64][SPITCH]
    float* Ks = Qs + BQ * SPITCH;          // [64][SPITCH]
    float* Vs = Ks + BKV * SPITCH;         // [64][SPITCH]
    float* Ps = Vs + BKV * SPITCH;         // [64][SPITCH]

    const int tid = threadIdx.x;
    const int tx = tid & 7;
    const int ty = tid >> 3;               // 0..15
    const int bh = blockIdx.y;
    const int b = bh >> 4;
    const int h = bh & 15;
    const int qt = blockIdx.x;
    const int q0 = qt * BQ;

    // Load Q tile, pre-scaled by 1/sqrt(64)
    {
        const int r = tid >> 1;
        const int c0 = (tid & 1) * 32;
        const float* src = qkv + (size_t)(b * SEQ + q0 + r) * NQKV + h * HD + c0;
#pragma unroll
        for (int c = 0; c < 32; c += 4) {
            float4 v = *reinterpret_cast<const float4*>(src + c);
            Qs[r * SPITCH + c0 + c + 0] = v.x * 0.125f;
            Qs[r * SPITCH + c0 + c + 1] = v.y * 0.125f;
            Qs[r * SPITCH + c0 + c + 2] = v.z * 0.125f;
            Qs[r * SPITCH + c0 + c + 3] = v.w * 0.125f;
        }
    }

    float m_i[4], l_i[4], acc[4][8];
#pragma unroll
    for (int i = 0; i < 4; i++) {
        m_i[i] = -INFINITY;
        l_i[i] = 0.f;
#pragma unroll
        for (int j = 0; j < 8; j++) acc[i][j] = 0.f;
    }

    int kstart = q0 - (WINDOW - 1);
    if (kstart < 0) kstart = 0;
    const int t0 = kstart >> 6;

    for (int t = t0; t <= qt; t++) {
        __syncthreads();   // previous iteration's Ks/Vs/Ps fully consumed
        {
            const int r = tid >> 1;
            const int c0 = (tid & 1) * 32;
            const float* ks = qkv + (size_t)(b * SEQ + t * BKV + r) * NQKV + DM + h * HD + c0;
            const float* vs = ks + DM;
#pragma unroll
            for (int c = 0; c < 32; c += 4) {
                float4 kv = *reinterpret_cast<const float4*>(ks + c);
                Ks[r * SPITCH + c0 + c + 0] = kv.x;
                Ks[r * SPITCH + c0 + c + 1] = kv.y;
                Ks[r * SPITCH + c0 + c + 2] = kv.z;
                Ks[r * SPITCH + c0 + c + 3] = kv.w;
                float4 vv = *reinterpret_cast<const float4*>(vs + c);
                Vs[r * SPITCH + c0 + c + 0] = vv.x;
                Vs[r * SPITCH + c0 + c + 1] = vv.y;
                Vs[r * SPITCH + c0 + c + 2] = vv.z;
                Vs[r * SPITCH + c0 + c + 3] = vv.w;
            }
        }
        __syncthreads();

        // S = Q @ K^T   (per thread: 4 rows x 8 cols)
        float s[4][8];
#pragma unroll
        for (int i = 0; i < 4; i++)
#pragma unroll
            for (int j = 0; j < 8; j++) s[i][j] = 0.f;

#pragma unroll 4
        for (int d = 0; d < HD; d++) {
            float qv[4];
#pragma unroll
            for (int i = 0; i < 4; i++) qv[i] = Qs[(ty * 4 + i) * SPITCH + d];
#pragma unroll
            for (int j = 0; j < 8; j++) {
                float kv = Ks[(tx + 8 * j) * SPITCH + d];
#pragma unroll
                for (int i = 0; i < 4; i++) s[i][j] = fmaf(qv[i], kv, s[i][j]);
            }
        }

        // mask + online softmax
#pragma unroll
        for (int i = 0; i < 4; i++) {
            const int qi = q0 + ty * 4 + i;
#pragma unroll
            for (int j = 0; j < 8; j++) {
                const int kg = t * BKV + tx + 8 * j;
                const int diff = qi - kg;
                if (diff < 0 || diff >= WINDOW) s[i][j] = -INFINITY;
            }
            float mrow = s[i][0];
#pragma unroll
            for (int j = 1; j < 8; j++) mrow = fmaxf(mrow, s[i][j]);
            mrow = fmaxf(mrow, __shfl_xor_sync(0xffffffffu, mrow, 1));
            mrow = fmaxf(mrow, __shfl_xor_sync(0xffffffffu, mrow, 2));
            mrow = fmaxf(mrow, __shfl_xor_sync(0xffffffffu, mrow, 4));

            const float mnew = fmaxf(m_i[i], mrow);
            const float mden = (mnew == -INFINITY) ? 0.f : mnew;
            const float sc = __expf(m_i[i] - mden);   // 0 when m_i == -inf
            float psum = 0.f;
#pragma unroll
            for (int j = 0; j < 8; j++) {
                float p = __expf(s[i][j] - mden);     // 0 for masked entries
                Ps[(ty * 4 + i) * SPITCH + tx + 8 * j] = p;
                psum += p;
            }
            psum += __shfl_xor_sync(0xffffffffu, psum, 1);
            psum += __shfl_xor_sync(0xffffffffu, psum, 2);
            psum += __shfl_xor_sync(0xffffffffu, psum, 4);

            l_i[i] = l_i[i] * sc + psum;
#pragma unroll
            for (int j = 0; j < 8; j++) acc[i][j] *= sc;
            m_i[i] = mnew;
        }
        __syncthreads();   // Ps fully written

        // acc += P @ V
#pragma unroll 4
        for (int kk = 0; kk < BKV; kk++) {
            float pv[4];
#pragma unroll
            for (int i = 0; i < 4; i++) pv[i] = Ps[(ty * 4 + i) * SPITCH + kk];
#pragma unroll
            for (int j = 0; j < 8; j++) {
                float vv = Vs[kk * SPITCH + tx + 8 * j];
#pragma unroll
                for (int i = 0; i < 4; i++) acc[i][j] = fmaf(pv[i], vv, acc[i][j]);
            }
        }
    }

    // epilogue: normalize, write (b, s, h, d) flattened as (b*s, h*64+d)
#pragma unroll
    for (int i = 0; i < 4; i++) {
        const float inv = 1.f / l_i[i];
        const size_t row = (size_t)(b * SEQ + q0 + ty * 4 + i) * DM + h * HD;
#pragma unroll
        for (int j = 0; j < 8; j++)
            outp[row + tx + 8 * j] = acc[i][j] * inv;
    }
}

// ---------------------------------------------------------------------------
extern "C" void kernel_launch(void* const* d_in, const int* in_sizes, int n_in,
                              void* d_out, int out_size)
{
    const float* x      = (const float*)d_in[0];   // (2,2048,1024)
    const float* qkv_w  = (const float*)d_in[1];   // (1024,3072)
    const float* qkv_b  = (const float*)d_in[2];   // (3072,)
    const float* out_w  = (const float*)d_in[3];   // (1024,1024)
    const float* out_b  = (const float*)d_in[4];   // (1024,)
    float* out = (float*)d_out;

    float *qkv_ptr = nullptr, *attn_ptr = nullptr;
    cudaGetSymbolAddress((void**)&qkv_ptr, g_qkv);
    cudaGetSymbolAddress((void**)&attn_ptr, g_attn);

    const size_t swa_smem = (size_t)4 * BQ * SPITCH * sizeof(float);  // 66560 B
    cudaFuncSetAttribute(swa_kernel, cudaFuncAttributeMaxDynamicSharedMemorySize,
                         (int)swa_smem);

    // 1) QKV projection + bias
    dim3 g1(NQKV / 128, MTOT / 128);
    sgemm_bias_kernel<<<g1, 256>>>(x, qkv_w, qkv_b, qkv_ptr, MTOT, NQKV, DM);

    // 2) sliding-window attention
    dim3 ga(SEQ / BQ, BATCH * NH);
    swa_kernel<<<ga, 128, swa_smem>>>(qkv_ptr, attn_ptr);

    // 3) output projection + bias
    dim3 g2(DM / 128, MTOT / 128);
    sgemm_bias_kernel<<<g2, 256>>>(attn_ptr, out_w, out_b, out, MTOT, DM, DM);
}

// round 2
// speedup vs baseline: 1.4309x; 1.4309x over previous
#include <cuda_runtime.h>
#include <math.h>
#include <stdint.h>

#define BATCH 2
#define SEQ 2048
#define NH 16
#define HD 64
#define DM 1024
#define WINDOW 512
#define MTOT (BATCH*SEQ)      // 4096
#define NQKV (3*DM)           // 3072

#define BQ 64
#define BKV 64
#define SPITCH 65

// tf32 GEMM tiling
#define BM 128
#define BN 128
#define BKT 32
#define APITCH 129
#define BPITCH 132

// scratch (allocation-free contract: __device__ globals)
__device__ float g_qkv[(size_t)MTOT * NQKV];   // (b*s, 3*H*hd)
__device__ float g_attn[(size_t)MTOT * DM];    // (b*s, H*hd)

__device__ __forceinline__ uint32_t f2tf32(float f) {
    uint32_t u;
    asm("cvt.rna.tf32.f32 %0, %1;" : "=r"(u) : "f"(f));
    return u;
}

__device__ __forceinline__ void mma_tf32(float c[4], const uint32_t a[4], const uint32_t b[2]) {
    asm volatile(
        "mma.sync.aligned.m16n8k8.row.col.f32.tf32.tf32.f32 "
        "{%0,%1,%2,%3}, {%4,%5,%6,%7}, {%8,%9}, {%0,%1,%2,%3};"
        : "+f"(c[0]), "+f"(c[1]), "+f"(c[2]), "+f"(c[3])
        : "r"(a[0]), "r"(a[1]), "r"(a[2]), "r"(a[3]), "r"(b[0]), "r"(b[1]));
}

// ---------------------------------------------------------------------------
// TF32 tensor-core GEMM: C[M,N] = A[M,K] @ B[K,N] + bias[N]
// 128x128 block, BK=32, 256 threads (8 warps as 2(M) x 4(N), warp tile 64x32)
// ---------------------------------------------------------------------------
__global__ __launch_bounds__(256) void tf32_gemm_bias(
    const float* __restrict__ A, const float* __restrict__ B,
    const float* __restrict__ bias, float* __restrict__ C,
    int M, int N, int K)
{
    extern __shared__ uint32_t dynsm[];
    uint32_t* As = dynsm;                       // [2][BKT][APITCH] k-major
    uint32_t* Bs = dynsm + 2 * BKT * APITCH;    // [2][BKT][BPITCH] k-major

    const int tid  = threadIdx.x;
    const int lane = tid & 31;
    const int warp = tid >> 5;
    const int wm = warp & 1;          // 0..1
    const int wn = warp >> 1;         // 0..3
    const int g  = lane >> 2;         // 0..7
    const int tg = lane & 3;          // 0..3

    const int rowBase = blockIdx.y * BM;
    const int colBase = blockIdx.x * BN;

    const float* Ag = A + (size_t)rowBase * K;
    const float* Bg = B + colBase;

    float acc[4][4][4];
#pragma unroll
    for (int i = 0; i < 4; i++)
#pragma unroll
        for (int j = 0; j < 4; j++)
#pragma unroll
            for (int c = 0; c < 4; c++) acc[i][j][c] = 0.f;

    float4 aReg[4], bReg[4];

    const int nkt = K / BKT;

#define LOAD_TILE(KT)                                                          \
    {                                                                          \
        _Pragma("unroll")                                                      \
        for (int f = 0; f < 4; f++) {                                          \
            int idx = tid + 256 * f;                                           \
            int ar = idx >> 3, ak = (idx & 7) * 4;                             \
            aReg[f] = *reinterpret_cast<const float4*>(                        \
                Ag + (size_t)ar * K + (KT) * BKT + ak);                        \
            int bk = idx >> 5, bn = (idx & 31) * 4;                            \
            bReg[f] = *reinterpret_cast<const float4*>(                        \
                Bg + (size_t)((KT) * BKT + bk) * N + bn);                      \
        }                                                                      \
    }

#define STORE_TILE(BUF)                                                        \
    {                                                                          \
        uint32_t* as = As + (BUF) * BKT * APITCH;                              \
        uint32_t* bs = Bs + (BUF) * BKT * BPITCH;                              \
        _Pragma("unroll")                                                      \
        for (int f = 0; f < 4; f++) {                                          \
            int idx = tid + 256 * f;                                           \
            int ar = idx >> 3, ak = (idx & 7) * 4;                             \
            as[(ak + 0) * APITCH + ar] = f2tf32(aReg[f].x);                    \
            as[(ak + 1) * APITCH + ar] = f2tf32(aReg[f].y);                    \
            as[(ak + 2) * APITCH + ar] = f2tf32(aReg[f].z);                    \
            as[(ak + 3) * APITCH + ar] = f2tf32(aReg[f].w);                    \
            int bk = idx >> 5, bn = (idx & 31) * 4;                            \
            uint4 bv;                                                          \
            bv.x = f2tf32(bReg[f].x); bv.y = f2tf32(bReg[f].y);                \
            bv.z = f2tf32(bReg[f].z); bv.w = f2tf32(bReg[f].w);                \
            *reinterpret_cast<uint4*>(&bs[bk * BPITCH + bn]) = bv;             \
        }                                                                      \
    }

    LOAD_TILE(0);
    STORE_TILE(0);
    __syncthreads();

    for (int kt = 0; kt < nkt; kt++) {
        const int buf = kt & 1;
        if (kt + 1 < nkt) LOAD_TILE(kt + 1);

        const uint32_t* as = As + buf * BKT * APITCH;
        const uint32_t* bs = Bs + buf * BKT * BPITCH;
#pragma unroll
        for (int ks = 0; ks < 4; ks++) {
            const int kk = ks * 8;
            uint32_t af[4][4];
#pragma unroll
            for (int mi = 0; mi < 4; mi++) {
                const int m = wm * 64 + mi * 16;
                af[mi][0] = as[(kk + tg) * APITCH + m + g];
                af[mi][1] = as[(kk + tg) * APITCH + m + g + 8];
                af[mi][2] = as[(kk + tg + 4) * APITCH + m + g];
                af[mi][3] = as[(kk + tg + 4) * APITCH + m + g + 8];
            }
            uint32_t bf[4][2];
#pragma unroll
            for (int nj = 0; nj < 4; nj++) {
                const int n = wn * 32 + nj * 8;
                bf[nj][0] = bs[(kk + tg) * BPITCH + n + g];
                bf[nj][1] = bs[(kk + tg + 4) * BPITCH + n + g];
            }
#pragma unroll
            for (int mi = 0; mi < 4; mi++)
#pragma unroll
                for (int nj = 0; nj < 4; nj++)
                    mma_tf32(acc[mi][nj], af[mi], bf[nj]);
        }

        if (kt + 1 < nkt) {
            STORE_TILE(!buf);
            __syncthreads();
        }
    }

    // epilogue
#pragma unroll
    for (int mi = 0; mi < 4; mi++) {
#pragma unroll
        for (int nj = 0; nj < 4; nj++) {
            const int col = colBase + wn * 32 + nj * 8 + tg * 2;
            const float bx = bias[col];
            const float by = bias[col + 1];
            const size_t r0 = (size_t)(rowBase + wm * 64 + mi * 16 + g);
            const size_t r1 = r0 + 8;
            float2 o0, o1;
            o0.x = acc[mi][nj][0] + bx; o0.y = acc[mi][nj][1] + by;
            o1.x = acc[mi][nj][2] + bx; o1.y = acc[mi][nj][3] + by;
            *reinterpret_cast<float2*>(C + r0 * N + col) = o0;
            *reinterpret_cast<float2*>(C + r1 * N + col) = o1;
        }
    }
#undef LOAD_TILE
#undef STORE_TILE
}

// ---------------------------------------------------------------------------
// Sliding-window attention (flash-style, fp32) — unchanged from round 1
// ---------------------------------------------------------------------------
__global__ __launch_bounds__(128) void swa_kernel(const float* __restrict__ qkv,
                                                  float* __restrict__ outp)
{
    extern __shared__ float sm[];
    float* Qs = sm;
    float* Ks = Qs + BQ * SPITCH;
    float* Vs = Ks + BKV * SPITCH;
    float* Ps = Vs + BKV * SPITCH;

    const int tid = threadIdx.x;
    const int tx = tid & 7;
    const int ty = tid >> 3;
    const int bh = blockIdx.y;
    const int b = bh >> 4;
    const int h = bh & 15;
    const int qt = blockIdx.x;
    const int q0 = qt * BQ;

    {
        const int r = tid >> 1;
        const int c0 = (tid & 1) * 32;
        const float* src = qkv + (size_t)(b * SEQ + q0 + r) * NQKV + h * HD + c0;
#pragma unroll
        for (int c = 0; c < 32; c += 4) {
            float4 v = *reinterpret_cast<const float4*>(src + c);
            Qs[r * SPITCH + c0 + c + 0] = v.x * 0.125f;
            Qs[r * SPITCH + c0 + c + 1] = v.y * 0.125f;
            Qs[r * SPITCH + c0 + c + 2] = v.z * 0.125f;
            Qs[r * SPITCH + c0 + c + 3] = v.w * 0.125f;
        }
    }

    float m_i[4], l_i[4], acc[4][8];
#pragma unroll
    for (int i = 0; i < 4; i++) {
        m_i[i] = -INFINITY;
        l_i[i] = 0.f;
#pragma unroll
        for (int j = 0; j < 8; j++) acc[i][j] = 0.f;
    }

    int kstart = q0 - (WINDOW - 1);
    if (kstart < 0) kstart = 0;
    const int t0 = kstart >> 6;

    for (int t = t0; t <= qt; t++) {
        __syncthreads();
        {
            const int r = tid >> 1;
            const int c0 = (tid & 1) * 32;
            const float* ks = qkv + (size_t)(b * SEQ + t * BKV + r) * NQKV + DM + h * HD + c0;
            const float* vs = ks + DM;
#pragma unroll
            for (int c = 0; c < 32; c += 4) {
                float4 kv = *reinterpret_cast<const float4*>(ks + c);
                Ks[r * SPITCH + c0 + c + 0] = kv.x;
                Ks[r * SPITCH + c0 + c + 1] = kv.y;
                Ks[r * SPITCH + c0 + c + 2] = kv.z;
                Ks[r * SPITCH + c0 + c + 3] = kv.w;
                float4 vv = *reinterpret_cast<const float4*>(vs + c);
                Vs[r * SPITCH + c0 + c + 0] = vv.x;
                Vs[r * SPITCH + c0 + c + 1] = vv.y;
                Vs[r * SPITCH + c0 + c + 2] = vv.z;
                Vs[r * SPITCH + c0 + c + 3] = vv.w;
            }
        }
        __syncthreads();

        float s[4][8];
#pragma unroll
        for (int i = 0; i < 4; i++)
#pragma unroll
            for (int j = 0; j < 8; j++) s[i][j] = 0.f;

#pragma unroll 4
        for (int d = 0; d < HD; d++) {
            float qv[4];
#pragma unroll
            for (int i = 0; i < 4; i++) qv[i] = Qs[(ty * 4 + i) * SPITCH + d];
#pragma unroll
            for (int j = 0; j < 8; j++) {
                float kv = Ks[(tx + 8 * j) * SPITCH + d];
#pragma unroll
                for (int i = 0; i < 4; i++) s[i][j] = fmaf(qv[i], kv, s[i][j]);
            }
        }

#pragma unroll
        for (int i = 0; i < 4; i++) {
            const int qi = q0 + ty * 4 + i;
#pragma unroll
            for (int j = 0; j < 8; j++) {
                const int kg = t * BKV + tx + 8 * j;
                const int diff = qi - kg;
                if (diff < 0 || diff >= WINDOW) s[i][j] = -INFINITY;
            }
            float mrow = s[i][0];
#pragma unroll
            for (int j = 1; j < 8; j++) mrow = fmaxf(mrow, s[i][j]);
            mrow = fmaxf(mrow, __shfl_xor_sync(0xffffffffu, mrow, 1));
            mrow = fmaxf(mrow, __shfl_xor_sync(0xffffffffu, mrow, 2));
            mrow = fmaxf(mrow, __shfl_xor_sync(0xffffffffu, mrow, 4));

            const float mnew = fmaxf(m_i[i], mrow);
            const float mden = (mnew == -INFINITY) ? 0.f : mnew;
            const float sc = __expf(m_i[i] - mden);
            float psum = 0.f;
#pragma unroll
            for (int j = 0; j < 8; j++) {
                float p = __expf(s[i][j] - mden);
                Ps[(ty * 4 + i) * SPITCH + tx + 8 * j] = p;
                psum += p;
            }
            psum += __shfl_xor_sync(0xffffffffu, psum, 1);
            psum += __shfl_xor_sync(0xffffffffu, psum, 2);
            psum += __shfl_xor_sync(0xffffffffu, psum, 4);

            l_i[i] = l_i[i] * sc + psum;
#pragma unroll
            for (int j = 0; j < 8; j++) acc[i][j] *= sc;
            m_i[i] = mnew;
        }
        __syncthreads();

#pragma unroll 4
        for (int kk = 0; kk < BKV; kk++) {
            float pv[4];
#pragma unroll
            for (int i = 0; i < 4; i++) pv[i] = Ps[(ty * 4 + i) * SPITCH + kk];
#pragma unroll
            for (int j = 0; j < 8; j++) {
                float vv = Vs[kk * SPITCH + tx + 8 * j];
#pragma unroll
                for (int i = 0; i < 4; i++) acc[i][j] = fmaf(pv[i], vv, acc[i][j]);
            }
        }
    }

#pragma unroll
    for (int i = 0; i < 4; i++) {
        const float inv = 1.f / l_i[i];
        const size_t row = (size_t)(b * SEQ + q0 + ty * 4 + i) * DM + h * HD;
#pragma unroll
        for (int j = 0; j < 8; j++)
            outp[row + tx + 8 * j] = acc[i][j] * inv;
    }
}

// ---------------------------------------------------------------------------
extern "C" void kernel_launch(void* const* d_in, const int* in_sizes, int n_in,
                              void* d_out, int out_size)
{
    const float* x      = (const float*)d_in[0];
    const float* qkv_w  = (const float*)d_in[1];
    const float* qkv_b  = (const float*)d_in[2];
    const float* out_w  = (const float*)d_in[3];
    const float* out_b  = (const float*)d_in[4];
    float* out = (float*)d_out;

    float *qkv_ptr = nullptr, *attn_ptr = nullptr;
    cudaGetSymbolAddress((void**)&qkv_ptr, g_qkv);
    cudaGetSymbolAddress((void**)&attn_ptr, g_attn);

    const size_t gemm_smem = (size_t)(2 * BKT * APITCH + 2 * BKT * BPITCH) * 4; // 66816
    cudaFuncSetAttribute(tf32_gemm_bias, cudaFuncAttributeMaxDynamicSharedMemorySize,
                         (int)gemm_smem);
    const size_t swa_smem = (size_t)4 * BQ * SPITCH * sizeof(float);
    cudaFuncSetAttribute(swa_kernel, cudaFuncAttributeMaxDynamicSharedMemorySize,
                         (int)swa_smem);

    // 1) QKV projection + bias  (tf32 tensor cores)
    dim3 g1(NQKV / BN, MTOT / BM);
    tf32_gemm_bias<<<g1, 256, gemm_smem>>>(x, qkv_w, qkv_b, qkv_ptr, MTOT, NQKV, DM);

    // 2) sliding-window attention
    dim3 ga(SEQ / BQ, BATCH * NH);
    swa_kernel<<<ga, 128, swa_smem>>>(qkv_ptr, attn_ptr);

    // 3) output projection + bias (tf32 tensor cores)
    dim3 g2(DM / BN, MTOT / BM);
    tf32_gemm_bias<<<g2, 256, gemm_smem>>>(attn_ptr, out_w, out_b, out, MTOT, DM, DM);
}

// round 3
// speedup vs baseline: 2.6597x; 1.8587x over previous
#include <cuda_runtime.h>
#include <math.h>
#include <stdint.h>

#define BATCH 2
#define SEQ 2048
#define NH 16
#define HD 64
#define DM 1024
#define WINDOW 512
#define MTOT (BATCH*SEQ)      // 4096
#define NQKV (3*DM)           // 3072

// GEMM tiling
#define GBM 128
#define GBN 128
#define GBK 16
#define GAP 20     // A smem pitch (floats), 80B rows -> 16B aligned
#define GBP 132    // B smem pitch
#define GSTAGES 3

// attention
#define ASP 68     // smem pitch for 64-wide tiles

__device__ float g_qkv[(size_t)MTOT * NQKV];
__device__ float g_attn[(size_t)MTOT * DM];

__device__ __forceinline__ uint32_t f2tf32(float f) {
    uint32_t u;
    asm("cvt.rna.tf32.f32 %0, %1;" : "=r"(u) : "f"(f));
    return u;
}
__device__ __forceinline__ float ex2(float x) {
    float y;
    asm("ex2.approx.ftz.f32 %0, %1;" : "=f"(y) : "f"(x));
    return y;
}
__device__ __forceinline__ void mma_tf32(float c[4], const uint32_t a[4], const uint32_t b[2]) {
    asm volatile(
        "mma.sync.aligned.m16n8k8.row.col.f32.tf32.tf32.f32 "
        "{%0,%1,%2,%3}, {%4,%5,%6,%7}, {%8,%9}, {%0,%1,%2,%3};"
        : "+f"(c[0]), "+f"(c[1]), "+f"(c[2]), "+f"(c[3])
        : "r"(a[0]), "r"(a[1]), "r"(a[2]), "r"(a[3]), "r"(b[0]), "r"(b[1]));
}
__device__ __forceinline__ void cp_async16(void* dst, const void* src) {
    uint32_t s = (uint32_t)__cvta_generic_to_shared(dst);
    asm volatile("cp.async.ca.shared.global [%0], [%1], 16;" :: "r"(s), "l"(src));
}

// ---------------------------------------------------------------------------
// TF32 GEMM v2: C[M,N] = A@B + bias. 128x128x16 tile, 128 threads,
// warp tile 64x64 (2x2 warps), 3-stage cp.async pipeline.
// ---------------------------------------------------------------------------
__global__ __launch_bounds__(128) void tf32_gemm_bias(
    const float* __restrict__ A, const float* __restrict__ B,
    const float* __restrict__ bias, float* __restrict__ C,
    int M, int N, int K)
{
    extern __shared__ float gsm[];
    float* As = gsm;                          // [GSTAGES][128][GAP]
    float* Bs = gsm + GSTAGES * 128 * GAP;    // [GSTAGES][16][GBP]

    const int tid  = threadIdx.x;
    const int lane = tid & 31;
    const int warp = tid >> 5;
    const int wm = warp & 1;
    const int wn = warp >> 1;
    const int g  = lane >> 2;
    const int tg = lane & 3;

    const int rowBase = blockIdx.y * GBM;
    const int colBase = blockIdx.x * GBN;
    const int nkt = K / GBK;

    float acc[4][8][4];
#pragma unroll
    for (int i = 0; i < 4; i++)
#pragma unroll
        for (int j = 0; j < 8; j++)
#pragma unroll
            for (int c = 0; c < 4; c++) acc[i][j][c] = 0.f;

    // loader geometry (4 x 16B per tensor per thread per stage)
    const int ar[4] = { (tid) >> 2, (tid + 128) >> 2, (tid + 256) >> 2, (tid + 384) >> 2 };
    const int ak = (tid & 3) * 4;
    const int bk[4] = { tid >> 5, (tid + 128) >> 5, (tid + 256) >> 5, (tid + 384) >> 5 };
    const int bn = (tid & 31) * 4;

#define ISSUE(KT, ST)                                                        \
    {                                                                        \
        float* as_ = As + (ST) * (128 * GAP);                                \
        float* bs_ = Bs + (ST) * (16 * GBP);                                 \
        _Pragma("unroll")                                                    \
        for (int f = 0; f < 4; f++) {                                        \
            cp_async16(as_ + ar[f] * GAP + ak,                               \
                       A + (size_t)(rowBase + ar[f]) * K + (KT) * GBK + ak); \
            cp_async16(bs_ + bk[f] * GBP + bn,                               \
                       B + (size_t)((KT) * GBK + bk[f]) * N + colBase + bn); \
        }                                                                    \
        asm volatile("cp.async.commit_group;");                              \
    }

    ISSUE(0, 0);
    ISSUE(1, 1);

    for (int kt = 0; kt < nkt; kt++) {
        if (kt + 1 < nkt) { asm volatile("cp.async.wait_group 1;"); }
        else              { asm volatile("cp.async.wait_group 0;"); }
        __syncthreads();

        const float* as = As + (kt % 3) * (128 * GAP);
        const float* bs = Bs + (kt % 3) * (16 * GBP);

#pragma unroll
        for (int ks = 0; ks < 2; ks++) {
            const int kk = ks * 8;
            uint32_t af[4][4];
#pragma unroll
            for (int mi = 0; mi < 4; mi++) {
                const int m = wm * 64 + mi * 16;
                af[mi][0] = f2tf32(as[(m + g) * GAP + kk + tg]);
                af[mi][1] = f2tf32(as[(m + g + 8) * GAP + kk + tg]);
                af[mi][2] = f2tf32(as[(m + g) * GAP + kk + tg + 4]);
                af[mi][3] = f2tf32(as[(m + g + 8) * GAP + kk + tg + 4]);
            }
            uint32_t bf[8][2];
#pragma unroll
            for (int nj = 0; nj < 8; nj++) {
                const int n = wn * 64 + nj * 8;
                bf[nj][0] = f2tf32(bs[(kk + tg) * GBP + n + g]);
                bf[nj][1] = f2tf32(bs[(kk + tg + 4) * GBP + n + g]);
            }
#pragma unroll
            for (int mi = 0; mi < 4; mi++)
#pragma unroll
                for (int nj = 0; nj < 8; nj++)
                    mma_tf32(acc[mi][nj], af[mi], bf[nj]);
        }

        if (kt + 2 < nkt) ISSUE(kt + 2, (kt + 2) % 3);
    }
#undef ISSUE

#pragma unroll
    for (int mi = 0; mi < 4; mi++) {
#pragma unroll
        for (int nj = 0; nj < 8; nj++) {
            const int col = colBase + wn * 64 + nj * 8 + tg * 2;
            const float bx = bias[col];
            const float by = bias[col + 1];
            const size_t r0 = (size_t)(rowBase + wm * 64 + mi * 16 + g);
            const size_t r1 = r0 + 8;
            float2 o0, o1;
            o0.x = acc[mi][nj][0] + bx; o0.y = acc[mi][nj][1] + by;
            o1.x = acc[mi][nj][2] + bx; o1.y = acc[mi][nj][3] + by;
            *reinterpret_cast<float2*>(C + r0 * N + col) = o0;
            *reinterpret_cast<float2*>(C + r1 * N + col) = o1;
        }
    }
}

// ---------------------------------------------------------------------------
// Sliding-window attention on tensor cores (tf32 mma, log2-domain softmax).
// Block = (qtile 64, b*h). 128 threads = 4 warps; warp w owns 16 query rows.
// ---------------------------------------------------------------------------
__global__ __launch_bounds__(128) void swa_mma_kernel(const float* __restrict__ qkv,
                                                      float* __restrict__ outp)
{
    extern __shared__ uint32_t asm_[];
    uint32_t* Qs = asm_;                  // [64][ASP] tf32, pre-scaled
    uint32_t* Ks = Qs + 64 * ASP;         // [key][hd] tf32
    uint32_t* Vt = Ks + 64 * ASP;         // [hd][key] tf32 (transposed)
    uint32_t* Ps = Vt + 64 * ASP;         // [q][key]  tf32

    const int tid  = threadIdx.x;
    const int lane = tid & 31;
    const int warp = tid >> 5;
    const int g  = lane >> 2;
    const int tg = lane & 3;
    const int bh = blockIdx.y;
    const int b = bh >> 4;
    const int h = bh & 15;
    const int qt = blockIdx.x;
    const int q0 = qt * 64;

    const float QSCALE = 0.125f * 1.4426950408889634f;  // 1/sqrt(64) * log2(e)

    // load Q tile (scaled, tf32)
    {
        const int r = tid >> 1;
        const int c0 = (tid & 1) * 32;
        const float* src = qkv + (size_t)(b * SEQ + q0 + r) * NQKV + h * HD + c0;
#pragma unroll
        for (int c = 0; c < 32; c += 4) {
            float4 v = *reinterpret_cast<const float4*>(src + c);
            uint4 u;
            u.x = f2tf32(v.x * QSCALE); u.y = f2tf32(v.y * QSCALE);
            u.z = f2tf32(v.z * QSCALE); u.w = f2tf32(v.w * QSCALE);
            *reinterpret_cast<uint4*>(&Qs[r * ASP + c0 + c]) = u;
        }
    }
    __syncthreads();

    // Q fragments (held in registers for the whole kernel)
    const int row0 = warp * 16 + g;   // warp-local query rows: row0, row0+8
    uint32_t qf[8][4];
#pragma unroll
    for (int ks = 0; ks < 8; ks++) {
        const int kk = ks * 8;
        qf[ks][0] = Qs[row0 * ASP + kk + tg];
        qf[ks][1] = Qs[(row0 + 8) * ASP + kk + tg];
        qf[ks][2] = Qs[row0 * ASP + kk + tg + 4];
        qf[ks][3] = Qs[(row0 + 8) * ASP + kk + tg + 4];
    }

    float oacc[8][4];
#pragma unroll
    for (int nb = 0; nb < 8; nb++)
#pragma unroll
        for (int c = 0; c < 4; c++) oacc[nb][c] = 0.f;
    float m0 = -INFINITY, m1 = -INFINITY, l0 = 0.f, l1 = 0.f;

    const int qg0 = q0 + row0;       // global query index, row g
    const int qg1 = qg0 + 8;

    int kstart = q0 - (WINDOW - 1);
    if (kstart < 0) kstart = 0;
    const int t0 = kstart >> 6;

    for (int t = t0; t <= qt; t++) {
        __syncthreads();  // all warps done reading previous Ks/Vt
        {
            const int r = tid >> 1;
            const int c0 = (tid & 1) * 32;
            const float* ks = qkv + (size_t)(b * SEQ + t * 64 + r) * NQKV + DM + h * HD + c0;
            const float* vs = ks + DM;
#pragma unroll
            for (int c = 0; c < 32; c += 4) {
                float4 kv = *reinterpret_cast<const float4*>(ks + c);
                uint4 u;
                u.x = f2tf32(kv.x); u.y = f2tf32(kv.y);
                u.z = f2tf32(kv.z); u.w = f2tf32(kv.w);
                *reinterpret_cast<uint4*>(&Ks[r * ASP + c0 + c]) = u;
                float4 vv = *reinterpret_cast<const float4*>(vs + c);
                Vt[(c0 + c + 0) * ASP + r] = f2tf32(vv.x);
                Vt[(c0 + c + 1) * ASP + r] = f2tf32(vv.y);
                Vt[(c0 + c + 2) * ASP + r] = f2tf32(vv.z);
                Vt[(c0 + c + 3) * ASP + r] = f2tf32(vv.w);
            }
        }
        __syncthreads();

        // S = Q @ K^T  (16x64 per warp)
        float sacc[8][4];
#pragma unroll
        for (int nb = 0; nb < 8; nb++)
#pragma unroll
            for (int c = 0; c < 4; c++) sacc[nb][c] = 0.f;

#pragma unroll
        for (int ks = 0; ks < 8; ks++) {
            const int kk = ks * 8;
#pragma unroll
            for (int nb = 0; nb < 8; nb++) {
                uint32_t bf[2];
                bf[0] = Ks[(nb * 8 + g) * ASP + kk + tg];
                bf[1] = Ks[(nb * 8 + g) * ASP + kk + tg + 4];
                mma_tf32(sacc[nb], qf[ks], bf);
            }
        }

        // mask + row max
        float mx0 = -INFINITY, mx1 = -INFINITY;
#pragma unroll
        for (int nb = 0; nb < 8; nb++) {
            const int kg0 = t * 64 + nb * 8 + tg * 2;
            const int kg1 = kg0 + 1;
            int d;
            d = qg0 - kg0; if (d < 0 || d >= WINDOW) sacc[nb][0] = -INFINITY;
            d = qg0 - kg1; if (d < 0 || d >= WINDOW) sacc[nb][1] = -INFINITY;
            d = qg1 - kg0; if (d < 0 || d >= WINDOW) sacc[nb][2] = -INFINITY;
            d = qg1 - kg1; if (d < 0 || d >= WINDOW) sacc[nb][3] = -INFINITY;
            mx0 = fmaxf(mx0, fmaxf(sacc[nb][0], sacc[nb][1]));
            mx1 = fmaxf(mx1, fmaxf(sacc[nb][2], sacc[nb][3]));
        }
        mx0 = fmaxf(mx0, __shfl_xor_sync(0xffffffffu, mx0, 1));
        mx0 = fmaxf(mx0, __shfl_xor_sync(0xffffffffu, mx0, 2));
        mx1 = fmaxf(mx1, __shfl_xor_sync(0xffffffffu, mx1, 1));
        mx1 = fmaxf(mx1, __shfl_xor_sync(0xffffffffu, mx1, 2));

        const float mn0 = fmaxf(m0, mx0), mn1 = fmaxf(m1, mx1);
        const float md0 = (mn0 == -INFINITY) ? 0.f : mn0;
        const float md1 = (mn1 == -INFINITY) ? 0.f : mn1;
        const float sc0 = ex2(m0 - md0);
        const float sc1 = ex2(m1 - md1);

        float ps0 = 0.f, ps1 = 0.f;
#pragma unroll
        for (int nb = 0; nb < 8; nb++) {
            float p00 = ex2(sacc[nb][0] - md0);
            float p01 = ex2(sacc[nb][1] - md0);
            float p10 = ex2(sacc[nb][2] - md1);
            float p11 = ex2(sacc[nb][3] - md1);
            ps0 += p00 + p01;
            ps1 += p10 + p11;
            uint2 u0, u1;
            u0.x = f2tf32(p00); u0.y = f2tf32(p01);
            u1.x = f2tf32(p10); u1.y = f2tf32(p11);
            *reinterpret_cast<uint2*>(&Ps[row0 * ASP + nb * 8 + tg * 2]) = u0;
            *reinterpret_cast<uint2*>(&Ps[(row0 + 8) * ASP + nb * 8 + tg * 2]) = u1;
        }
        ps0 += __shfl_xor_sync(0xffffffffu, ps0, 1);
        ps0 += __shfl_xor_sync(0xffffffffu, ps0, 2);
        ps1 += __shfl_xor_sync(0xffffffffu, ps1, 1);
        ps1 += __shfl_xor_sync(0xffffffffu, ps1, 2);

        l0 = l0 * sc0 + ps0;
        l1 = l1 * sc1 + ps1;
        m0 = mn0; m1 = mn1;
#pragma unroll
        for (int nb = 0; nb < 8; nb++) {
            oacc[nb][0] *= sc0; oacc[nb][1] *= sc0;
            oacc[nb][2] *= sc1; oacc[nb][3] *= sc1;
        }
        __syncwarp();  // Ps visible within warp

        // O += P @ V   (A = P rows [row0..], B = Vt)
#pragma unroll
        for (int ks = 0; ks < 8; ks++) {
            const int kk = ks * 8;
            uint32_t af[4];
            af[0] = Ps[row0 * ASP + kk + tg];
            af[1] = Ps[(row0 + 8) * ASP + kk + tg];
            af[2] = Ps[row0 * ASP + kk + tg + 4];
            af[3] = Ps[(row0 + 8) * ASP + kk + tg + 4];
#pragma unroll
            for (int nb = 0; nb < 8; nb++) {
                uint32_t bf[2];
                bf[0] = Vt[(nb * 8 + g) * ASP + kk + tg];
                bf[1] = Vt[(nb * 8 + g) * ASP + kk + tg + 4];
                mma_tf32(oacc[nb], af, bf);
            }
        }
    }

    // epilogue
    const float inv0 = 1.f / l0, inv1 = 1.f / l1;
    const size_t gr0 = (size_t)(b * SEQ + qg0) * DM + h * HD;
    const size_t gr1 = (size_t)(b * SEQ + qg1) * DM + h * HD;
#pragma unroll
    for (int nb = 0; nb < 8; nb++) {
        const int col = nb * 8 + tg * 2;
        float2 o0, o1;
        o0.x = oacc[nb][0] * inv0; o0.y = oacc[nb][1] * inv0;
        o1.x = oacc[nb][2] * inv1; o1.y = oacc[nb][3] * inv1;
        *reinterpret_cast<float2*>(outp + gr0 + col) = o0;
        *reinterpret_cast<float2*>(outp + gr1 + col) = o1;
    }
}

// ---------------------------------------------------------------------------
extern "C" void kernel_launch(void* const* d_in, const int* in_sizes, int n_in,
                              void* d_out, int out_size)
{
    const float* x      = (const float*)d_in[0];
    const float* qkv_w  = (const float*)d_in[1];
    const float* qkv_b  = (const float*)d_in[2];
    const float* out_w  = (const float*)d_in[3];
    const float* out_b  = (const float*)d_in[4];
    float* out = (float*)d_out;

    float *qkv_ptr = nullptr, *attn_ptr = nullptr;
    cudaGetSymbolAddress((void**)&qkv_ptr, g_qkv);
    cudaGetSymbolAddress((void**)&attn_ptr, g_attn);

    const size_t gemm_smem = (size_t)GSTAGES * (128 * GAP + 16 * GBP) * 4;  // 56064
    cudaFuncSetAttribute(tf32_gemm_bias, cudaFuncAttributeMaxDynamicSharedMemorySize,
                         (int)gemm_smem);
    const size_t swa_smem = (size_t)4 * 64 * ASP * 4;                       // 69632
    cudaFuncSetAttribute(swa_mma_kernel, cudaFuncAttributeMaxDynamicSharedMemorySize,
                         (int)swa_smem);

    dim3 g1(NQKV / GBN, MTOT / GBM);
    tf32_gemm_bias<<<g1, 128, gemm_smem>>>(x, qkv_w, qkv_b, qkv_ptr, MTOT, NQKV, DM);

    dim3 ga(SEQ / 64, BATCH * NH);
    swa_mma_kernel<<<ga, 128, swa_smem>>>(qkv_ptr, attn_ptr);

    dim3 g2(DM / GBN, MTOT / GBM);
    tf32_gemm_bias<<<g2, 128, gemm_smem>>>(attn_ptr, out_w, out_b, out, MTOT, DM, DM);
}

// round 4
// speedup vs baseline: 2.7240x; 1.0241x over previous
#include <cuda_runtime.h>
#include <math.h>
#include <stdint.h>

#define BATCH 2
#define SEQ 2048
#define NH 16
#define HD 64
#define DM 1024
#define WINDOW 512
#define MTOT (BATCH*SEQ)      // 4096
#define NQKV (3*DM)           // 3072

// GEMM tiling
#define GBM 128
#define GBN 128
#define GBK 16
#define GAP 20     // A smem pitch
#define GBP 136    // B smem pitch (mod 32 == 8 -> conflict-free bf loads)
#define GSTAGES 3

// attention pitches
#define KP 68      // K/Q/P pitch (mod 32 == 4)
#define VP 72      // V pitch (mod 32 == 8)

__device__ float g_qkv[(size_t)MTOT * NQKV];
__device__ float g_attn[(size_t)MTOT * DM];
__device__ float g_xc[(size_t)MTOT * DM];
__device__ float g_w1[(size_t)DM * NQKV];
__device__ float g_w2[(size_t)DM * DM];

__device__ __forceinline__ uint32_t f2tf32(float f) {
    uint32_t u;
    asm("cvt.rna.tf32.f32 %0, %1;" : "=r"(u) : "f"(f));
    return u;
}
__device__ __forceinline__ float ex2(float x) {
    float y;
    asm("ex2.approx.ftz.f32 %0, %1;" : "=f"(y) : "f"(x));
    return y;
}
__device__ __forceinline__ void mma_tf32(float c[4], const uint32_t a[4], const uint32_t b[2]) {
    asm volatile(
        "mma.sync.aligned.m16n8k8.row.col.f32.tf32.tf32.f32 "
        "{%0,%1,%2,%3}, {%4,%5,%6,%7}, {%8,%9}, {%0,%1,%2,%3};"
        : "+f"(c[0]), "+f"(c[1]), "+f"(c[2]), "+f"(c[3])
        : "r"(a[0]), "r"(a[1]), "r"(a[2]), "r"(a[3]), "r"(b[0]), "r"(b[1]));
}
__device__ __forceinline__ void cp_async16(void* dst, const void* src) {
    uint32_t s = (uint32_t)__cvta_generic_to_shared(dst);
    asm volatile("cp.async.ca.shared.global [%0], [%1], 16;" :: "r"(s), "l"(src));
}

// elementwise tf32 pre-round (n % 1024 == 0)
__global__ __launch_bounds__(256) void cvt_tf32_kernel(const float* __restrict__ in,
                                                       float* __restrict__ outp, int n4)
{
    int idx = blockIdx.x * 256 + threadIdx.x;
    int stride = gridDim.x * 256;
    for (; idx < n4; idx += stride) {
        float4 v = reinterpret_cast<const float4*>(in)[idx];
        uint4 u;
        u.x = f2tf32(v.x); u.y = f2tf32(v.y); u.z = f2tf32(v.z); u.w = f2tf32(v.w);
        reinterpret_cast<uint4*>(outp)[idx] = u;
    }
}

// ---------------------------------------------------------------------------
// TF32 GEMM: inputs pre-rounded to tf32 bits. 128x128x16 tile, 128 threads,
// warp tile 64x64, 3-stage cp.async. ROUND=1 -> write tf32-rounded output.
// ---------------------------------------------------------------------------
template<int ROUND>
__global__ __launch_bounds__(128) void tf32_gemm_bias(
    const float* __restrict__ A, const float* __restrict__ B,
    const float* __restrict__ bias, float* __restrict__ C,
    int M, int N, int K)
{
    extern __shared__ float gsm[];
    float* As = gsm;                          // [GSTAGES][128][GAP]
    float* Bs = gsm + GSTAGES * 128 * GAP;    // [GSTAGES][16][GBP]

    const int tid  = threadIdx.x;
    const int lane = tid & 31;
    const int warp = tid >> 5;
    const int wm = warp & 1;
    const int wn = warp >> 1;
    const int g  = lane >> 2;
    const int tg = lane & 3;

    const int rowBase = blockIdx.y * GBM;
    const int colBase = blockIdx.x * GBN;
    const int nkt = K / GBK;

    float acc[4][8][4];
#pragma unroll
    for (int i = 0; i < 4; i++)
#pragma unroll
        for (int j = 0; j < 8; j++)
#pragma unroll
            for (int c = 0; c < 4; c++) acc[i][j][c] = 0.f;

    const int ar[4] = { (tid) >> 2, (tid + 128) >> 2, (tid + 256) >> 2, (tid + 384) >> 2 };
    const int ak = (tid & 3) * 4;
    const int bk[4] = { tid >> 5, (tid + 128) >> 5, (tid + 256) >> 5, (tid + 384) >> 5 };
    const int bn = (tid & 31) * 4;

#define ISSUE(KT, ST)                                                        \
    {                                                                        \
        float* as_ = As + (ST) * (128 * GAP);                                \
        float* bs_ = Bs + (ST) * (16 * GBP);                                 \
        _Pragma("unroll")                                                    \
        for (int f = 0; f < 4; f++) {                                        \
            cp_async16(as_ + ar[f] * GAP + ak,                               \
                       A + (size_t)(rowBase + ar[f]) * K + (KT) * GBK + ak); \
            cp_async16(bs_ + bk[f] * GBP + bn,                               \
                       B + (size_t)((KT) * GBK + bk[f]) * N + colBase + bn); \
        }                                                                    \
        asm volatile("cp.async.commit_group;");                              \
    }

    ISSUE(0, 0);
    ISSUE(1, 1);

    for (int kt = 0; kt < nkt; kt++) {
        if (kt + 1 < nkt) { asm volatile("cp.async.wait_group 1;"); }
        else              { asm volatile("cp.async.wait_group 0;"); }
        __syncthreads();

        const float* as = As + (kt % 3) * (128 * GAP);
        const float* bs = Bs + (kt % 3) * (16 * GBP);

#pragma unroll
        for (int ks = 0; ks < 2; ks++) {
            const int kk = ks * 8;
            uint32_t af[4][4];
#pragma unroll
            for (int mi = 0; mi < 4; mi++) {
                const int m = wm * 64 + mi * 16;
                af[mi][0] = __float_as_uint(as[(m + g) * GAP + kk + tg]);
                af[mi][1] = __float_as_uint(as[(m + g + 8) * GAP + kk + tg]);
                af[mi][2] = __float_as_uint(as[(m + g) * GAP + kk + tg + 4]);
                af[mi][3] = __float_as_uint(as[(m + g + 8) * GAP + kk + tg + 4]);
            }
            uint32_t bf[8][2];
#pragma unroll
            for (int nj = 0; nj < 8; nj++) {
                const int n = wn * 64 + nj * 8;
                bf[nj][0] = __float_as_uint(bs[(kk + tg) * GBP + n + g]);
                bf[nj][1] = __float_as_uint(bs[(kk + tg + 4) * GBP + n + g]);
            }
#pragma unroll
            for (int mi = 0; mi < 4; mi++)
#pragma unroll
                for (int nj = 0; nj < 8; nj++)
                    mma_tf32(acc[mi][nj], af[mi], bf[nj]);
        }

        if (kt + 2 < nkt) ISSUE(kt + 2, (kt + 2) % 3);
    }
#undef ISSUE

#pragma unroll
    for (int mi = 0; mi < 4; mi++) {
#pragma unroll
        for (int nj = 0; nj < 8; nj++) {
            const int col = colBase + wn * 64 + nj * 8 + tg * 2;
            const float bx = bias[col];
            const float by = bias[col + 1];
            const size_t r0 = (size_t)(rowBase + wm * 64 + mi * 16 + g);
            const size_t r1 = r0 + 8;
            float v00 = acc[mi][nj][0] + bx, v01 = acc[mi][nj][1] + by;
            float v10 = acc[mi][nj][2] + bx, v11 = acc[mi][nj][3] + by;
            if (ROUND) {
                v00 = __uint_as_float(f2tf32(v00));
                v01 = __uint_as_float(f2tf32(v01));
                v10 = __uint_as_float(f2tf32(v10));
                v11 = __uint_as_float(f2tf32(v11));
            }
            float2 o0 = {v00, v01}, o1 = {v10, v11};
            *reinterpret_cast<float2*>(C + r0 * N + col) = o0;
            *reinterpret_cast<float2*>(C + r1 * N + col) = o1;
        }
    }
}

// ---------------------------------------------------------------------------
// Sliding-window attention on tensor cores. qkv already tf32-rounded.
// Block = (qtile 64, b*h), 128 threads = 4 warps, warp owns 16 query rows.
// K/V double-buffered via cp.async; V kept row-major (no transpose).
// ---------------------------------------------------------------------------
__global__ __launch_bounds__(128) void swa_mma_kernel(const float* __restrict__ qkv,
                                                      float* __restrict__ outp)
{
    extern __shared__ float sm[];
    float* Qs = sm;                      // [64][KP]
    float* Ks = Qs + 64 * KP;            // [2][64][KP]
    float* Vs = Ks + 2 * 64 * KP;        // [2][64][VP]
    float* Ps = Vs + 2 * 64 * VP;        // [64][KP]

    const int tid  = threadIdx.x;
    const int lane = tid & 31;
    const int warp = tid >> 5;
    const int g  = lane >> 2;
    const int tg = lane & 3;
    const int bh = blockIdx.y;
    const int b = bh >> 4;
    const int h = bh & 15;
    const int qt = blockIdx.x;
    const int q0 = qt * 64;

    const float QSCALE = 0.125f * 1.4426950408889634f;  // 1/sqrt(64) * log2(e)

    const int r  = tid >> 1;
    const int c0 = (tid & 1) * 32;

    // load Q tile (scale + re-round to tf32)
    {
        const float* src = qkv + (size_t)(b * SEQ + q0 + r) * NQKV + h * HD + c0;
#pragma unroll
        for (int c = 0; c < 32; c += 4) {
            float4 v = *reinterpret_cast<const float4*>(src + c);
            uint4 u;
            u.x = f2tf32(v.x * QSCALE); u.y = f2tf32(v.y * QSCALE);
            u.z = f2tf32(v.z * QSCALE); u.w = f2tf32(v.w * QSCALE);
            *reinterpret_cast<uint4*>(&Qs[r * KP + c0 + c]) = u;
        }
    }

    int kstart = q0 - (WINDOW - 1);
    if (kstart < 0) kstart = 0;
    const int t0 = kstart >> 6;

#define PREFETCH(T, ST)                                                          \
    {                                                                            \
        const float* ksrc = qkv + (size_t)(b * SEQ + (T) * 64 + r) * NQKV        \
                            + DM + h * HD + c0;                                  \
        const float* vsrc = ksrc + DM;                                           \
        float* kd = Ks + (ST) * 64 * KP + r * KP + c0;                           \
        float* vd = Vs + (ST) * 64 * VP + r * VP + c0;                           \
        _Pragma("unroll")                                                        \
        for (int c = 0; c < 32; c += 4) {                                        \
            cp_async16(kd + c, ksrc + c);                                        \
            cp_async16(vd + c, vsrc + c);                                        \
        }                                                                        \
        asm volatile("cp.async.commit_group;");                                  \
    }

    PREFETCH(t0, 0);
    __syncthreads();   // Qs visible

    // Q fragments in registers
    const int row0 = warp * 16 + g;
    uint32_t qf[8][4];
#pragma unroll
    for (int ks = 0; ks < 8; ks++) {
        const int kk = ks * 8;
        qf[ks][0] = __float_as_uint(Qs[row0 * KP + kk + tg]);
        qf[ks][1] = __float_as_uint(Qs[(row0 + 8) * KP + kk + tg]);
        qf[ks][2] = __float_as_uint(Qs[row0 * KP + kk + tg + 4]);
        qf[ks][3] = __float_as_uint(Qs[(row0 + 8) * KP + kk + tg + 4]);
    }

    float oacc[8][4];
#pragma unroll
    for (int nb = 0; nb < 8; nb++)
#pragma unroll
        for (int c = 0; c < 4; c++) oacc[nb][c] = 0.f;
    float m0 = -INFINITY, m1 = -INFINITY, l0 = 0.f, l1 = 0.f;

    const int qg0 = q0 + row0;
    const int qg1 = qg0 + 8;

    int buf = 0;
    for (int t = t0; t <= qt; t++) {
        if (t < qt) {
            PREFETCH(t + 1, buf ^ 1);
            asm volatile("cp.async.wait_group 1;");
        } else {
            asm volatile("cp.async.wait_group 0;");
        }
        __syncthreads();

        const float* ks_ = Ks + buf * 64 * KP;
        const float* vs_ = Vs + buf * 64 * VP;

        // S = Q @ K^T (16x64 per warp)
        float sacc[8][4];
#pragma unroll
        for (int nb = 0; nb < 8; nb++)
#pragma unroll
            for (int c = 0; c < 4; c++) sacc[nb][c] = 0.f;

#pragma unroll
        for (int ks = 0; ks < 8; ks++) {
            const int kk = ks * 8;
#pragma unroll
            for (int nb = 0; nb < 8; nb++) {
                uint32_t bf[2];
                bf[0] = __float_as_uint(ks_[(nb * 8 + g) * KP + kk + tg]);
                bf[1] = __float_as_uint(ks_[(nb * 8 + g) * KP + kk + tg + 4]);
                mma_tf32(sacc[nb], qf[ks], bf);
            }
        }

        // mask only boundary tiles (delta == 0 diagonal, delta == 512 trailing)
        const int delta = q0 - t * 64;
        if (delta == 0 || delta == WINDOW) {
#pragma unroll
            for (int nb = 0; nb < 8; nb++) {
                const int kg0 = t * 64 + nb * 8 + tg * 2;
                const int kg1 = kg0 + 1;
                int d;
                d = qg0 - kg0; if (d < 0 || d >= WINDOW) sacc[nb][0] = -INFINITY;
                d = qg0 - kg1; if (d < 0 || d >= WINDOW) sacc[nb][1] = -INFINITY;
                d = qg1 - kg0; if (d < 0 || d >= WINDOW) sacc[nb][2] = -INFINITY;
                d = qg1 - kg1; if (d < 0 || d >= WINDOW) sacc[nb][3] = -INFINITY;
            }
        }

        float mx0 = -INFINITY, mx1 = -INFINITY;
#pragma unroll
        for (int nb = 0; nb < 8; nb++) {
            mx0 = fmaxf(mx0, fmaxf(sacc[nb][0], sacc[nb][1]));
            mx1 = fmaxf(mx1, fmaxf(sacc[nb][2], sacc[nb][3]));
        }
        mx0 = fmaxf(mx0, __shfl_xor_sync(0xffffffffu, mx0, 1));
        mx0 = fmaxf(mx0, __shfl_xor_sync(0xffffffffu, mx0, 2));
        mx1 = fmaxf(mx1, __shfl_xor_sync(0xffffffffu, mx1, 1));
        mx1 = fmaxf(mx1, __shfl_xor_sync(0xffffffffu, mx1, 2));

        const float mn0 = fmaxf(m0, mx0), mn1 = fmaxf(m1, mx1);
        const float md0 = (mn0 == -INFINITY) ? 0.f : mn0;
        const float md1 = (mn1 == -INFINITY) ? 0.f : mn1;
        const float sc0 = ex2(m0 - md0);
        const float sc1 = ex2(m1 - md1);

        float ps0 = 0.f, ps1 = 0.f;
#pragma unroll
        for (int nb = 0; nb < 8; nb++) {
            float p00 = ex2(sacc[nb][0] - md0);
            float p01 = ex2(sacc[nb][1] - md0);
            float p10 = ex2(sacc[nb][2] - md1);
            float p11 = ex2(sacc[nb][3] - md1);
            ps0 += p00 + p01;
            ps1 += p10 + p11;
            uint2 u0, u1;
            u0.x = f2tf32(p00); u0.y = f2tf32(p01);
            u1.x = f2tf32(p10); u1.y = f2tf32(p11);
            *reinterpret_cast<uint2*>(&Ps[row0 * KP + nb * 8 + tg * 2]) = u0;
            *reinterpret_cast<uint2*>(&Ps[(row0 + 8) * KP + nb * 8 + tg * 2]) = u1;
        }
        ps0 += __shfl_xor_sync(0xffffffffu, ps0, 1);
        ps0 += __shfl_xor_sync(0xffffffffu, ps0, 2);
        ps1 += __shfl_xor_sync(0xffffffffu, ps1, 1);
        ps1 += __shfl_xor_sync(0xffffffffu, ps1, 2);

        l0 = l0 * sc0 + ps0;
        l1 = l1 * sc1 + ps1;
        m0 = mn0; m1 = mn1;
#pragma unroll
        for (int nb = 0; nb < 8; nb++) {
            oacc[nb][0] *= sc0; oacc[nb][1] *= sc0;
            oacc[nb][2] *= sc1; oacc[nb][3] *= sc1;
        }
        __syncwarp();  // Ps (per-warp rows) visible

        // O += P @ V  (V row-major: B-frag = V[k][n])
#pragma unroll
        for (int ks = 0; ks < 8; ks++) {
            const int kk = ks * 8;
            uint32_t af[4];
            af[0] = __float_as_uint(Ps[row0 * KP + kk + tg]);
            af[1] = __float_as_uint(Ps[(row0 + 8) * KP + kk + tg]);
            af[2] = __float_as_uint(Ps[row0 * KP + kk + tg + 4]);
            af[3] = __float_as_uint(Ps[(row0 + 8) * KP + kk + tg + 4]);
#pragma unroll
            for (int nb = 0; nb < 8; nb++) {
                uint32_t bf[2];
                bf[0] = __float_as_uint(vs_[(kk + tg) * VP + nb * 8 + g]);
                bf[1] = __float_as_uint(vs_[(kk + tg + 4) * VP + nb * 8 + g]);
                mma_tf32(oacc[nb], af, bf);
            }
        }

        __syncthreads();  // all warps done with buf before it is overwritten
        buf ^= 1;
    }
#undef PREFETCH

    // epilogue (tf32-rounded: feeds GEMM2)
    const float inv0 = 1.f / l0, inv1 = 1.f / l1;
    const size_t gr0 = (size_t)(b * SEQ + qg0) * DM + h * HD;
    const size_t gr1 = (size_t)(b * SEQ + qg1) * DM + h * HD;
#pragma unroll
    for (int nb = 0; nb < 8; nb++) {
        const int col = nb * 8 + tg * 2;
        uint2 o0, o1;
        o0.x = f2tf32(oacc[nb][0] * inv0); o0.y = f2tf32(oacc[nb][1] * inv0);
        o1.x = f2tf32(oacc[nb][2] * inv1); o1.y = f2tf32(oacc[nb][3] * inv1);
        *reinterpret_cast<uint2*>(outp + gr0 + col) = o0;
        *reinterpret_cast<uint2*>(outp + gr1 + col) = o1;
    }
}

// ---------------------------------------------------------------------------
extern "C" void kernel_launch(void* const* d_in, const int* in_sizes, int n_in,
                              void* d_out, int out_size)
{
    const float* x      = (const float*)d_in[0];
    const float* qkv_w  = (const float*)d_in[1];
    const float* qkv_b  = (const float*)d_in[2];
    const float* out_w  = (const float*)d_in[3];
    const float* out_b  = (const float*)d_in[4];
    float* out = (float*)d_out;

    float *qkv_ptr, *attn_ptr, *xc_ptr, *w1_ptr, *w2_ptr;
    cudaGetSymbolAddress((void**)&qkv_ptr, g_qkv);
    cudaGetSymbolAddress((void**)&attn_ptr, g_attn);
    cudaGetSymbolAddress((void**)&xc_ptr, g_xc);
    cudaGetSymbolAddress((void**)&w1_ptr, g_w1);
    cudaGetSymbolAddress((void**)&w2_ptr, g_w2);

    const size_t gemm_smem = (size_t)(GSTAGES * (128 * GAP + 16 * GBP)) * 4;
    cudaFuncSetAttribute(tf32_gemm_bias<0>, cudaFuncAttributeMaxDynamicSharedMemorySize,
                         (int)gemm_smem);
    cudaFuncSetAttribute(tf32_gemm_bias<1>, cudaFuncAttributeMaxDynamicSharedMemorySize,
                         (int)gemm_smem);
    const size_t swa_smem = (size_t)(64 * KP + 2 * 64 * KP + 2 * 64 * VP + 64 * KP) * 4;
    cudaFuncSetAttribute(swa_mma_kernel, cudaFuncAttributeMaxDynamicSharedMemorySize,
                         (int)swa_smem);

    // pre-round inputs/weights to tf32
    cvt_tf32_kernel<<<1024, 256>>>(x, xc_ptr, MTOT * DM / 4);
    cvt_tf32_kernel<<<1024, 256>>>(qkv_w, w1_ptr, DM * NQKV / 4);
    cvt_tf32_kernel<<<512, 256>>>(out_w, w2_ptr, DM * DM / 4);

    dim3 g1(NQKV / GBN, MTOT / GBM);
    tf32_gemm_bias<1><<<g1, 128, gemm_smem>>>(xc_ptr, w1_ptr, qkv_b, qkv_ptr, MTOT, NQKV, DM);

    dim3 ga(SEQ / 64, BATCH * NH);
    swa_mma_kernel<<<ga, 128, swa_smem>>>(qkv_ptr, attn_ptr);

    dim3 g2(DM / GBN, MTOT / GBM);
    tf32_gemm_bias<0><<<g2, 128, gemm_smem>>>(attn_ptr, w2_ptr, out_b, out, MTOT, DM, DM);
}

// round 5
// speedup vs baseline: 2.7993x; 1.0276x over previous
#include <cuda_runtime.h>
#include <math.h>
#include <stdint.h>

#define BATCH 2
#define SEQ 2048
#define NH 16
#define HD 64
#define DM 1024
#define WINDOW 512
#define MTOT (BATCH*SEQ)      // 4096
#define NQKV (3*DM)           // 3072

// GEMM tiling
#define GBM 128
#define GBN 128
#define GBK 32
#define GAP 36     // A smem pitch (row-major [m][k])
#define GBP 136    // B smem pitch
#define GSTAGES 3

// attention pitches
#define KP 68
#define VP 72

__device__ float g_qkv[(size_t)MTOT * NQKV];
__device__ float g_attn[(size_t)MTOT * DM];
__device__ float g_xc[(size_t)MTOT * DM];
__device__ float g_w1[(size_t)DM * NQKV];
__device__ float g_w2[(size_t)DM * DM];

__device__ __forceinline__ uint32_t f2tf32(float f) {
    uint32_t u;
    asm("cvt.rna.tf32.f32 %0, %1;" : "=r"(u) : "f"(f));
    return u;
}
__device__ __forceinline__ float ex2(float x) {
    float y;
    asm("ex2.approx.ftz.f32 %0, %1;" : "=f"(y) : "f"(x));
    return y;
}
__device__ __forceinline__ void mma_tf32(float c[4], const uint32_t a[4], const uint32_t b[2]) {
    asm volatile(
        "mma.sync.aligned.m16n8k8.row.col.f32.tf32.tf32.f32 "
        "{%0,%1,%2,%3}, {%4,%5,%6,%7}, {%8,%9}, {%0,%1,%2,%3};"
        : "+f"(c[0]), "+f"(c[1]), "+f"(c[2]), "+f"(c[3])
        : "r"(a[0]), "r"(a[1]), "r"(a[2]), "r"(a[3]), "r"(b[0]), "r"(b[1]));
}
__device__ __forceinline__ void cp_async16(void* dst, const void* src) {
    uint32_t s = (uint32_t)__cvta_generic_to_shared(dst);
    asm volatile("cp.async.ca.shared.global [%0], [%1], 16;" :: "r"(s), "l"(src));
}

// elementwise tf32 pre-round
__global__ __launch_bounds__(256) void cvt_tf32_kernel(const float* __restrict__ in,
                                                       float* __restrict__ outp, int n4)
{
    int idx = blockIdx.x * 256 + threadIdx.x;
    int stride = gridDim.x * 256;
    for (; idx < n4; idx += stride) {
        float4 v = reinterpret_cast<const float4*>(in)[idx];
        uint4 u;
        u.x = f2tf32(v.x); u.y = f2tf32(v.y); u.z = f2tf32(v.z); u.w = f2tf32(v.w);
        reinterpret_cast<uint4*>(outp)[idx] = u;
    }
}

// ---------------------------------------------------------------------------
// TF32 GEMM v3: 128x128x32 tile, 128 threads, warp tile 64x64, 3-stage
// cp.async pipeline with issue-before-compute. Inputs pre-rounded.
// ---------------------------------------------------------------------------
template<int ROUND>
__global__ __launch_bounds__(128) void tf32_gemm_bias(
    const float* __restrict__ A, const float* __restrict__ B,
    const float* __restrict__ bias, float* __restrict__ C,
    int M, int N, int K)
{
    extern __shared__ float gsm[];
    float* As = gsm;                          // [GSTAGES][128][GAP]
    float* Bs = gsm + GSTAGES * 128 * GAP;    // [GSTAGES][32][GBP]

    const int tid  = threadIdx.x;
    const int lane = tid & 31;
    const int warp = tid >> 5;
    const int wm = warp & 1;
    const int wn = warp >> 1;
    const int g  = lane >> 2;
    const int tg = lane & 3;

    const int rowBase = blockIdx.y * GBM;
    const int colBase = blockIdx.x * GBN;
    const int nkt = K / GBK;

    float acc[4][8][4];
#pragma unroll
    for (int i = 0; i < 4; i++)
#pragma unroll
        for (int j = 0; j < 8; j++)
#pragma unroll
            for (int c = 0; c < 4; c++) acc[i][j][c] = 0.f;

#define ISSUE(KT, ST)                                                          \
    {                                                                          \
        float* as_ = As + (ST) * (128 * GAP);                                  \
        float* bs_ = Bs + (ST) * (32 * GBP);                                   \
        _Pragma("unroll")                                                      \
        for (int f = 0; f < 8; f++) {                                          \
            int idx = tid + 128 * f;                                           \
            int arow = idx >> 3, acol = (idx & 7) * 4;                         \
            cp_async16(as_ + arow * GAP + acol,                                \
                       A + (size_t)(rowBase + arow) * K + (KT) * GBK + acol);  \
            int bk = idx >> 5, bn = (idx & 31) * 4;                            \
            cp_async16(bs_ + bk * GBP + bn,                                    \
                       B + (size_t)((KT) * GBK + bk) * N + colBase + bn);      \
        }                                                                      \
        asm volatile("cp.async.commit_group;");                                \
    }

    ISSUE(0, 0);
    ISSUE(1, 1);

    for (int kt = 0; kt < nkt; kt++) {
        if (kt + 1 < nkt) { asm volatile("cp.async.wait_group 1;"); }
        else              { asm volatile("cp.async.wait_group 0;"); }
        __syncthreads();

        if (kt + 2 < nkt) ISSUE(kt + 2, (kt + 2) % 3);

        const float* as = As + (kt % 3) * (128 * GAP);
        const float* bs = Bs + (kt % 3) * (32 * GBP);

#pragma unroll
        for (int ks = 0; ks < 4; ks++) {
            const int kk = ks * 8;
            uint32_t af[4][4];
#pragma unroll
            for (int mi = 0; mi < 4; mi++) {
                const int m = wm * 64 + mi * 16;
                af[mi][0] = __float_as_uint(as[(m + g) * GAP + kk + tg]);
                af[mi][1] = __float_as_uint(as[(m + g + 8) * GAP + kk + tg]);
                af[mi][2] = __float_as_uint(as[(m + g) * GAP + kk + tg + 4]);
                af[mi][3] = __float_as_uint(as[(m + g + 8) * GAP + kk + tg + 4]);
            }
            uint32_t bf[8][2];
#pragma unroll
            for (int nj = 0; nj < 8; nj++) {
                const int n = wn * 64 + nj * 8;
                bf[nj][0] = __float_as_uint(bs[(kk + tg) * GBP + n + g]);
                bf[nj][1] = __float_as_uint(bs[(kk + tg + 4) * GBP + n + g]);
            }
#pragma unroll
            for (int mi = 0; mi < 4; mi++)
#pragma unroll
                for (int nj = 0; nj < 8; nj++)
                    mma_tf32(acc[mi][nj], af[mi], bf[nj]);
        }
    }
#undef ISSUE

#pragma unroll
    for (int mi = 0; mi < 4; mi++) {
#pragma unroll
        for (int nj = 0; nj < 8; nj++) {
            const int col = colBase + wn * 64 + nj * 8 + tg * 2;
            const float bx = bias[col];
            const float by = bias[col + 1];
            const size_t r0 = (size_t)(rowBase + wm * 64 + mi * 16 + g);
            const size_t r1 = r0 + 8;
            float v00 = acc[mi][nj][0] + bx, v01 = acc[mi][nj][1] + by;
            float v10 = acc[mi][nj][2] + bx, v11 = acc[mi][nj][3] + by;
            if (ROUND) {
                v00 = __uint_as_float(f2tf32(v00));
                v01 = __uint_as_float(f2tf32(v01));
                v10 = __uint_as_float(f2tf32(v10));
                v11 = __uint_as_float(f2tf32(v11));
            }
            float2 o0 = {v00, v01}, o1 = {v10, v11};
            *reinterpret_cast<float2*>(C + r0 * N + col) = o0;
            *reinterpret_cast<float2*>(C + r1 * N + col) = o1;
        }
    }
}

// ---------------------------------------------------------------------------
// Sliding-window attention, tf32 MMA. 128 threads / 4 warps, 3 blocks/SM.
// K double-buffered (1 tile ahead), V single-buffered (load overlaps S+softmax),
// Ps overlays Qs (Q lives in registers after prologue).
// ---------------------------------------------------------------------------
__global__ __launch_bounds__(128, 3) void swa_mma_kernel(const float* __restrict__ qkv,
                                                         float* __restrict__ outp)
{
    extern __shared__ float sm[];
    float* Qs = sm;                      // [64][KP]  (later reused as Ps)
    float* Ps = sm;
    float* Ks = Qs + 64 * KP;            // [2][64][KP]
    float* Vs = Ks + 2 * 64 * KP;        // [64][VP]

    const int tid  = threadIdx.x;
    const int lane = tid & 31;
    const int warp = tid >> 5;
    const int g  = lane >> 2;
    const int tg = lane & 3;
    const int bh = blockIdx.y;
    const int b = bh >> 4;
    const int h = bh & 15;
    const int qt = blockIdx.x;
    const int q0 = qt * 64;

    const float QSCALE = 0.125f * 1.4426950408889634f;  // 1/sqrt(64) * log2(e)

    const int r  = tid >> 1;
    const int c0 = (tid & 1) * 32;

#define PREFETCH_K(T, ST)                                                        \
    {                                                                            \
        const float* ksrc = qkv + (size_t)(b * SEQ + (T) * 64 + r) * NQKV        \
                            + DM + h * HD + c0;                                  \
        float* kd = Ks + (ST) * 64 * KP + r * KP + c0;                           \
        _Pragma("unroll")                                                        \
        for (int c = 0; c < 32; c += 4) cp_async16(kd + c, ksrc + c);            \
        asm volatile("cp.async.commit_group;");                                  \
    }
#define PREFETCH_V(T)                                                            \
    {                                                                            \
        const float* vsrc = qkv + (size_t)(b * SEQ + (T) * 64 + r) * NQKV        \
                            + 2 * DM + h * HD + c0;                              \
        float* vd = Vs + r * VP + c0;                                            \
        _Pragma("unroll")                                                        \
        for (int c = 0; c < 32; c += 4) cp_async16(vd + c, vsrc + c);            \
        asm volatile("cp.async.commit_group;");                                  \
    }

    // Q tile -> smem (scaled, tf32)
    {
        const float* src = qkv + (size_t)(b * SEQ + q0 + r) * NQKV + h * HD + c0;
#pragma unroll
        for (int c = 0; c < 32; c += 4) {
            float4 v = *reinterpret_cast<const float4*>(src + c);
            uint4 u;
            u.x = f2tf32(v.x * QSCALE); u.y = f2tf32(v.y * QSCALE);
            u.z = f2tf32(v.z * QSCALE); u.w = f2tf32(v.w * QSCALE);
            *reinterpret_cast<uint4*>(&Qs[r * KP + c0 + c]) = u;
        }
    }

    int kstart = q0 - (WINDOW - 1);
    if (kstart < 0) kstart = 0;
    const int t0 = kstart >> 6;

    // prologue commits: {K(t0)}, {V(t0)}, {K(t0+1) if any}
    PREFETCH_K(t0, t0 & 1);
    PREFETCH_V(t0);
    if (t0 < qt) PREFETCH_K(t0 + 1, (t0 + 1) & 1);

    __syncthreads();   // Qs visible

    // Q fragments in registers (Qs smem becomes Ps afterward)
    const int row0 = warp * 16 + g;
    uint32_t qf[8][4];
#pragma unroll
    for (int ks = 0; ks < 8; ks++) {
        const int kk = ks * 8;
        qf[ks][0] = __float_as_uint(Qs[row0 * KP + kk + tg]);
        qf[ks][1] = __float_as_uint(Qs[(row0 + 8) * KP + kk + tg]);
        qf[ks][2] = __float_as_uint(Qs[row0 * KP + kk + tg + 4]);
        qf[ks][3] = __float_as_uint(Qs[(row0 + 8) * KP + kk + tg + 4]);
    }

    float oacc[8][4];
#pragma unroll
    for (int nb = 0; nb < 8; nb++)
#pragma unroll
        for (int c = 0; c < 4; c++) oacc[nb][c] = 0.f;
    float m0 = -INFINITY, m1 = -INFINITY, l0 = 0.f, l1 = 0.f;

    const int qg0 = q0 + row0;
    const int qg1 = qg0 + 8;

    for (int t = t0; t <= qt; t++) {
        // K(t) ready: allow pending {V(t), K(t+1)} when t<qt else {V(t)}
        if (t < qt) { asm volatile("cp.async.wait_group 2;"); }
        else        { asm volatile("cp.async.wait_group 1;"); }
        __syncthreads();   // K stage (t&1) + (t>t0: V freed) visible/consistent

        const float* ks_ = Ks + (t & 1) * 64 * KP;

        // S = Q @ K^T (16x64 per warp)
        float sacc[8][4];
#pragma unroll
        for (int nb = 0; nb < 8; nb++)
#pragma unroll
            for (int c = 0; c < 4; c++) sacc[nb][c] = 0.f;

#pragma unroll
        for (int ks = 0; ks < 8; ks++) {
            const int kk = ks * 8;
#pragma unroll
            for (int nb = 0; nb < 8; nb++) {
                uint32_t bf[2];
                bf[0] = __float_as_uint(ks_[(nb * 8 + g) * KP + kk + tg]);
                bf[1] = __float_as_uint(ks_[(nb * 8 + g) * KP + kk + tg + 4]);
                mma_tf32(sacc[nb], qf[ks], bf);
            }
        }

        // boundary masking only
        const int delta = q0 - t * 64;
        if (delta == 0 || delta == WINDOW) {
#pragma unroll
            for (int nb = 0; nb < 8; nb++) {
                const int kg0 = t * 64 + nb * 8 + tg * 2;
                const int kg1 = kg0 + 1;
                int d;
                d = qg0 - kg0; if (d < 0 || d >= WINDOW) sacc[nb][0] = -INFINITY;
                d = qg0 - kg1; if (d < 0 || d >= WINDOW) sacc[nb][1] = -INFINITY;
                d = qg1 - kg0; if (d < 0 || d >= WINDOW) sacc[nb][2] = -INFINITY;
                d = qg1 - kg1; if (d < 0 || d >= WINDOW) sacc[nb][3] = -INFINITY;
            }
        }

        float mx0 = -INFINITY, mx1 = -INFINITY;
#pragma unroll
        for (int nb = 0; nb < 8; nb++) {
            mx0 = fmaxf(mx0, fmaxf(sacc[nb][0], sacc[nb][1]));
            mx1 = fmaxf(mx1, fmaxf(sacc[nb][2], sacc[nb][3]));
        }
        mx0 = fmaxf(mx0, __shfl_xor_sync(0xffffffffu, mx0, 1));
        mx0 = fmaxf(mx0, __shfl_xor_sync(0xffffffffu, mx0, 2));
        mx1 = fmaxf(mx1, __shfl_xor_sync(0xffffffffu, mx1, 1));
        mx1 = fmaxf(mx1, __shfl_xor_sync(0xffffffffu, mx1, 2));

        const float mn0 = fmaxf(m0, mx0), mn1 = fmaxf(m1, mx1);
        const float md0 = (mn0 == -INFINITY) ? 0.f : mn0;
        const float md1 = (mn1 == -INFINITY) ? 0.f : mn1;
        const float sc0 = ex2(m0 - md0);
        const float sc1 = ex2(m1 - md1);

        float ps0 = 0.f, ps1 = 0.f;
#pragma unroll
        for (int nb = 0; nb < 8; nb++) {
            float p00 = ex2(sacc[nb][0] - md0);
            float p01 = ex2(sacc[nb][1] - md0);
            float p10 = ex2(sacc[nb][2] - md1);
            float p11 = ex2(sacc[nb][3] - md1);
            ps0 += p00 + p01;
            ps1 += p10 + p11;
            uint2 u0, u1;
            u0.x = f2tf32(p00); u0.y = f2tf32(p01);
            u1.x = f2tf32(p10); u1.y = f2tf32(p11);
            *reinterpret_cast<uint2*>(&Ps[row0 * KP + nb * 8 + tg * 2]) = u0;
            *reinterpret_cast<uint2*>(&Ps[(row0 + 8) * KP + nb * 8 + tg * 2]) = u1;
        }
        ps0 += __shfl_xor_sync(0xffffffffu, ps0, 1);
        ps0 += __shfl_xor_sync(0xffffffffu, ps0, 2);
        ps1 += __shfl_xor_sync(0xffffffffu, ps1, 1);
        ps1 += __shfl_xor_sync(0xffffffffu, ps1, 2);

        l0 = l0 * sc0 + ps0;
        l1 = l1 * sc1 + ps1;
        m0 = mn0; m1 = mn1;
#pragma unroll
        for (int nb = 0; nb < 8; nb++) {
            oacc[nb][0] *= sc0; oacc[nb][1] *= sc0;
            oacc[nb][2] *= sc1; oacc[nb][3] *= sc1;
        }

        // V(t) ready: allow pending {K(t+1)} when t<qt
        if (t < qt) { asm volatile("cp.async.wait_group 1;"); }
        else        { asm volatile("cp.async.wait_group 0;"); }
        __syncwarp();   // own Ps rows visible to own warp (per-warp rows only)

        // O += P @ V
#pragma unroll
        for (int ks = 0; ks < 8; ks++) {
            const int kk = ks * 8;
            uint32_t af[4];
            af[0] = __float_as_uint(Ps[row0 * KP + kk + tg]);
            af[1] = __float_as_uint(Ps[(row0 + 8) * KP + kk + tg]);
            af[2] = __float_as_uint(Ps[row0 * KP + kk + tg + 4]);
            af[3] = __float_as_uint(Ps[(row0 + 8) * KP + kk + tg + 4]);
#pragma unroll
            for (int nb = 0; nb < 8; nb++) {
                uint32_t bf[2];
                bf[0] = __float_as_uint(Vs[(kk + tg) * VP + nb * 8 + g]);
                bf[1] = __float_as_uint(Vs[(kk + tg + 4) * VP + nb * 8 + g]);
                mma_tf32(oacc[nb], af, bf);
            }
        }

        __syncthreads();   // all warps finished reading Vs & K stage
        if (t < qt) {
            PREFETCH_V(t + 1);
            if (t + 1 < qt) PREFETCH_K(t + 2, t & 1);
        }
    }
#undef PREFETCH_K
#undef PREFETCH_V

    // epilogue (tf32-rounded: feeds GEMM2)
    const float inv0 = 1.f / l0, inv1 = 1.f / l1;
    const size_t gr0 = (size_t)(b * SEQ + qg0) * DM + h * HD;
    const size_t gr1 = (size_t)(b * SEQ + qg1) * DM + h * HD;
#pragma unroll
    for (int nb = 0; nb < 8; nb++) {
        const int col = nb * 8 + tg * 2;
        uint2 o0, o1;
        o0.x = f2tf32(oacc[nb][0] * inv0); o0.y = f2tf32(oacc[nb][1] * inv0);
        o1.x = f2tf32(oacc[nb][2] * inv1); o1.y = f2tf32(oacc[nb][3] * inv1);
        *reinterpret_cast<uint2*>(outp + gr0 + col) = o0;
        *reinterpret_cast<uint2*>(outp + gr1 + col) = o1;
    }
}

// ---------------------------------------------------------------------------
extern "C" void kernel_launch(void* const* d_in, const int* in_sizes, int n_in,
                              void* d_out, int out_size)
{
    const float* x      = (const float*)d_in[0];
    const float* qkv_w  = (const float*)d_in[1];
    const float* qkv_b  = (const float*)d_in[2];
    const float* out_w  = (const float*)d_in[3];
    const float* out_b  = (const float*)d_in[4];
    float* out = (float*)d_out;

    float *qkv_ptr, *attn_ptr, *xc_ptr, *w1_ptr, *w2_ptr;
    cudaGetSymbolAddress((void**)&qkv_ptr, g_qkv);
    cudaGetSymbolAddress((void**)&attn_ptr, g_attn);
    cudaGetSymbolAddress((void**)&xc_ptr, g_xc);
    cudaGetSymbolAddress((void**)&w1_ptr, g_w1);
    cudaGetSymbolAddress((void**)&w2_ptr, g_w2);

    const size_t gemm_smem = (size_t)(GSTAGES * (128 * GAP + 32 * GBP)) * 4;  // 107520
    cudaFuncSetAttribute(tf32_gemm_bias<0>, cudaFuncAttributeMaxDynamicSharedMemorySize,
                         (int)gemm_smem);
    cudaFuncSetAttribute(tf32_gemm_bias<1>, cudaFuncAttributeMaxDynamicSharedMemorySize,
                         (int)gemm_smem);
    const size_t swa_smem = (size_t)(64 * KP + 2 * 64 * KP + 64 * VP) * 4;    // 70656
    cudaFuncSetAttribute(swa_mma_kernel, cudaFuncAttributeMaxDynamicSharedMemorySize,
                         (int)swa_smem);

    // pre-round inputs/weights to tf32
    cvt_tf32_kernel<<<1024, 256>>>(x, xc_ptr, MTOT * DM / 4);
    cvt_tf32_kernel<<<1024, 256>>>(qkv_w, w1_ptr, DM * NQKV / 4);
    cvt_tf32_kernel<<<512, 256>>>(out_w, w2_ptr, DM * DM / 4);

    dim3 g1(NQKV / GBN, MTOT / GBM);
    tf32_gemm_bias<1><<<g1, 128, gemm_smem>>>(xc_ptr, w1_ptr, qkv_b, qkv_ptr, MTOT, NQKV, DM);

    dim3 ga(SEQ / 64, BATCH * NH);
    swa_mma_kernel<<<ga, 128, swa_smem>>>(qkv_ptr, attn_ptr);

    dim3 g2(DM / GBN, MTOT / GBM);
    tf32_gemm_bias<0><<<g2, 128, gemm_smem>>>(attn_ptr, w2_ptr, out_b, out, MTOT, DM, DM);
}